// round 4
// baseline (speedup 1.0000x reference)
// O3onO2 tensor product — persistent 2-CTA/SM fp32 kernel, f32x2 FMAs.
// Per CTA (fixed output block lo): W for its 4 paths resident in smem;
// loop over 16-row tiles: combine (direct from global) -> z in smem -> GEMM.
#include <cuda_runtime.h>
#include <cstdint>

#define NROWS   65536
#define TILE_M  16
#define NTHREADS 256
#define NTILES  (NROWS / TILE_M)   // 4096

#define W_STRIDE 66
#define W_PER    (64 * W_STRIDE)       // 4224 floats per path
#define Z_OFF    (4 * W_PER)           // 16896 floats
#define Z_FLOATS (64 * 7 * TILE_M)     // 7168 floats (max NZ=7)
#define SMEM_FLOATS (Z_OFF + Z_FLOATS) // 24064
#define SMEM_BYTES  (SMEM_FLOATS * 4)  // 96256 B -> 2 CTAs/SM

// per-lo persistent CTA counts, proportional to work (NZtot = 4,10,14,16)
#define CNT0 27
#define CNT1 67
#define CNT2 94
#define CNT3 108   // total 296 = 2*148

__device__ __forceinline__ constexpr int blk_off(int l) {
    return l == 0 ? 0 : (l == 1 ? 64 : (l == 2 ? 256 : 576));
}

__device__ __forceinline__ unsigned long long dup2(float a) {
    unsigned long long r;
    asm("mov.b64 %0, {%1, %1};" : "=l"(r) : "f"(a));
    return r;
}
__device__ __forceinline__ void fma2(unsigned long long& d,
                                     unsigned long long a,
                                     unsigned long long b) {
    asm("fma.rn.f32x2 %0, %1, %2, %0;" : "+l"(d) : "l"(a), "l"(b));
}

// ---- combine: read x block tile straight from global (coalesced half-warp
// sweeps, partner value is a few bytes away -> same L1 line), write z ----
template <int LO, int LI>
__device__ __forceinline__ void combine(
    float* __restrict__ zs, const float* __restrict__ gx,
    const float* __restrict__ hz, const float* __restrict__ hpg,
    const float* __restrict__ hng)
{
    constexpr int W21 = 2 * LI + 1;
    constexpr int L   = 64 * W21;
    constexpr int MM  = LO < LI ? LO : LI;
    constexpr int NZ  = 2 * MM + 1;
    constexpr int P   = LO * 4 + LI;
    const int tid = threadIdx.x;
    const int r   = ((tid >> 5) << 1) | ((tid >> 4) & 1);  // row 0..15
    const int j0  = tid & 15;
    const float h0 = __ldg(hz + P);
    float hp[MM ? MM : 1], hn[MM ? MM : 1];
#pragma unroll
    for (int m = 0; m < MM; m++) {
        hp[m] = __ldg(hpg + P * 3 + m);
        hn[m] = __ldg(hng + P * 3 + m);
    }
    const float* xr = gx + (size_t)r * 1024;
#pragma unroll 2
    for (int j = j0; j < L; j += 16) {
        const int k = j / W21;
        const int c = j - k * W21;
        const float xv = __ldg(xr + j);
        if (c == LI) {
            zs[(k * NZ) * TILE_M + r] = h0 * xv;
        } else if (c > LI) {
#pragma unroll
            for (int mm = 1; mm <= MM; mm++) {
                if (c == LI + mm) {
                    const float xn = __ldg(xr + j - 2 * mm);
                    zs[(k * NZ + 2 * mm - 1) * TILE_M + r] =
                        hp[mm - 1] * xv + hn[mm - 1] * xn;
                    zs[(k * NZ + 2 * mm) * TILE_M + r] =
                        hp[mm - 1] * xn - hn[mm - 1] * xv;
                }
            }
        }
    }
}

// ---- GEMM: acc[oo][c] += z(k,zc,rowpair) * W[li](k, og*2+oo) ----
template <int LO, int LI>
__device__ __forceinline__ void gemm(
    const float* __restrict__ sm, unsigned long long (&acc)[2][2 * LO + 1],
    int rg, int og)
{
    constexpr int MM = LO < LI ? LO : LI;
    constexpr int NZ = 2 * MM + 1;
    const unsigned long long* zb =
        reinterpret_cast<const unsigned long long*>(sm + Z_OFF);
    const float* wsl = sm + LI * W_PER + og * 2;
#pragma unroll 4
    for (int k = 0; k < 64; k++) {
        const float2 wv = *reinterpret_cast<const float2*>(wsl + k * W_STRIDE);
        const unsigned long long w0 = dup2(wv.x);
        const unsigned long long w1 = dup2(wv.y);
#pragma unroll
        for (int zc = 0; zc < NZ; zc++) {
            const int c = (zc == 0) ? LO
                         : ((zc & 1) ? LO + (zc + 1) / 2 : LO - zc / 2);
            const unsigned long long z = zb[(k * NZ + zc) * (TILE_M / 2) + rg];
            fma2(acc[0][c], z, w0);
            fma2(acc[1][c], z, w1);
        }
    }
}

template <int LO>
__device__ __forceinline__ void run(
    float* __restrict__ sm, const float* __restrict__ x,
    const float* __restrict__ wts, const float* __restrict__ hz,
    const float* __restrict__ hpg, const float* __restrict__ hng,
    float* __restrict__ out, int t0, int tstep)
{
    constexpr int NC  = 2 * LO + 1;
    constexpr int SEG = 64 * NC;       // floats per output row segment
    constexpr int NQ  = SEG / 4;       // float4 per row
    const int tid = threadIdx.x;
    const int rg  = tid >> 5;          // warp id -> row pair
    const int og  = tid & 31;          // lane -> 2 output channels

    // ---- stage W (transposed: ws[i*66 + o]), once per CTA ----
#pragma unroll
    for (int li = 0; li < 4; li++) {
        const float* gw = wts + (LO * 4 + li) * 4096;
        for (int idx = tid; idx < 4096; idx += NTHREADS) {
            const int o = idx >> 6, i = idx & 63;
            sm[li * W_PER + i * W_STRIDE + o] = gw[idx];
        }
    }

    for (int t = t0; t < NTILES; t += tstep) {
        unsigned long long acc[2][NC];
#pragma unroll
        for (int a = 0; a < 2; a++)
#pragma unroll
            for (int c = 0; c < NC; c++) acc[a][c] = 0ull;

        const float* gx = x + (size_t)t * TILE_M * 1024;

        __syncthreads();  // z free (prev copy-out done); W visible on 1st iter
        combine<LO, 0>(sm + Z_OFF, gx + blk_off(0), hz, hpg, hng);
        __syncthreads();
        gemm<LO, 0>(sm, acc, rg, og);
        __syncthreads();
        combine<LO, 1>(sm + Z_OFF, gx + blk_off(1), hz, hpg, hng);
        __syncthreads();
        gemm<LO, 1>(sm, acc, rg, og);
        __syncthreads();
        combine<LO, 2>(sm + Z_OFF, gx + blk_off(2), hz, hpg, hng);
        __syncthreads();
        gemm<LO, 2>(sm, acc, rg, og);
        __syncthreads();
        combine<LO, 3>(sm + Z_OFF, gx + blk_off(3), hz, hpg, hng);
        __syncthreads();
        gemm<LO, 3>(sm, acc, rg, og);

        // ---- stage output tile in smem (global layout), coalesced f4 store --
        __syncthreads();                 // all warps done reading z
        float* smo = sm + Z_OFF;
#pragma unroll
        for (int oo = 0; oo < 2; oo++) {
            const int o = og * 2 + oo;
#pragma unroll
            for (int c = 0; c < NC; c++) {
                const unsigned long long v = acc[oo][c];
                smo[(rg * 2) * SEG + o * NC + c] =
                    __uint_as_float((unsigned)(v & 0xffffffffu));
                smo[(rg * 2 + 1) * SEG + o * NC + c] =
                    __uint_as_float((unsigned)(v >> 32));
            }
        }
        __syncthreads();
        float* go = out + (size_t)t * TILE_M * 1024 + blk_off(LO);
        for (int i = tid; i < TILE_M * NQ; i += NTHREADS) {
            const int r = i / NQ;
            const int j = i - r * NQ;
            *reinterpret_cast<float4*>(go + (size_t)r * 1024 + j * 4) =
                *reinterpret_cast<const float4*>(smo + r * SEG + j * 4);
        }
        // next-iteration leading __syncthreads protects z reuse vs copy-out
    }
}

extern "C" __global__ void __launch_bounds__(NTHREADS, 2)
tp_kernel(const float* __restrict__ x, const float* __restrict__ wts,
          const float* __restrict__ hz, const float* __restrict__ hpg,
          const float* __restrict__ hng, float* __restrict__ out)
{
    extern __shared__ float sm[];
    const int b = blockIdx.x;
    if (b < CNT0) {
        run<0>(sm, x, wts, hz, hpg, hng, out, b, CNT0);
    } else if (b < CNT0 + CNT1) {
        run<1>(sm, x, wts, hz, hpg, hng, out, b - CNT0, CNT1);
    } else if (b < CNT0 + CNT1 + CNT2) {
        run<2>(sm, x, wts, hz, hpg, hng, out, b - CNT0 - CNT1, CNT2);
    } else {
        run<3>(sm, x, wts, hz, hpg, hng, out, b - CNT0 - CNT1 - CNT2, CNT3);
    }
}

extern "C" void kernel_launch(void* const* d_in, const int* in_sizes, int n_in,
                              void* d_out, int out_size)
{
    const float* x   = (const float*)d_in[0];
    const float* wts = (const float*)d_in[1];
    const float* hz  = (const float*)d_in[2];
    const float* hpg = (const float*)d_in[3];
    const float* hng = (const float*)d_in[4];
    float* out = (float*)d_out;

    cudaFuncSetAttribute(tp_kernel, cudaFuncAttributeMaxDynamicSharedMemorySize,
                         SMEM_BYTES);
    tp_kernel<<<CNT0 + CNT1 + CNT2 + CNT3, NTHREADS, SMEM_BYTES>>>(
        x, wts, hz, hpg, hng, out);
}

// round 6
// speedup vs baseline: 6.0346x; 6.0346x over previous
// O3onO2 tensor product — fused fp32 kernel, f32x2-packed FMAs, TILE_M=32,
// 2 CTAs/SM (77.8KB smem). Per CTA = one (lo, 32-row tile):
//   per li: [stage W + combine z direct-from-global] -> barrier -> GEMM.
// z layout [col][row] with stride 34 (2-way max write conflicts, 8B-aligned
// row-pair reads). Output staged through smem, float4 stores.
#include <cuda_runtime.h>
#include <cstdint>

#define NROWS    65536
#define TILE_M   32
#define NTHREADS 256
#define W_STRIDE 66
#define Z_STRIDE 34
#define W_OFF    0
#define Z_OFF    4224                       // 64*66 floats for W
#define SMEM_FLOATS (Z_OFF + 64 * 7 * Z_STRIDE)   // 4224 + 15232 = 19456
#define SMEM_BYTES  (SMEM_FLOATS * 4)             // 77824 B -> 2 CTAs/SM

__device__ __forceinline__ constexpr int blk_off(int l) {
    return l == 0 ? 0 : (l == 1 ? 64 : (l == 2 ? 256 : 576));
}

__device__ __forceinline__ unsigned long long dup2(float a) {
    unsigned long long r;
    asm("mov.b64 %0, {%1, %1};" : "=l"(r) : "f"(a));
    return r;
}
__device__ __forceinline__ void fma2(unsigned long long& d,
                                     unsigned long long a,
                                     unsigned long long b) {
    asm("fma.rn.f32x2 %0, %1, %2, %0;" : "+l"(d) : "l"(a), "l"(b));
}

// ---- phase 1 of each li: stage W (transposed, L2-hot) + combine z from global
template <int LO, int LI>
__device__ __forceinline__ void stage_combine(
    float* __restrict__ sm, const float* __restrict__ gx,
    const float* __restrict__ wts, const float* __restrict__ hz,
    const float* __restrict__ hpg, const float* __restrict__ hng)
{
    constexpr int W21 = 2 * LI + 1;
    constexpr int MM  = LO < LI ? LO : LI;
    constexpr int NZ  = 2 * MM + 1;
    constexpr int P   = LO * 4 + LI;
    const int tid = threadIdx.x;

    // stage W transposed: ws[i*66 + o] = W[o][i]   (2-way write conflicts)
    const float* gw = wts + P * 4096;
#pragma unroll
    for (int s = 0; s < 16; s++) {
        const int idx = tid + s * NTHREADS;
        const int o = idx >> 6, i = idx & 63;
        sm[W_OFF + i * W_STRIDE + o] = __ldg(gw + idx);
    }

    // combine: z[k*NZ+zc][r] = h-combo of x[r, k*(2LI+1) + LI +- m]
    const float h0 = __ldg(hz + P);
    float hp[MM ? MM : 1], hn[MM ? MM : 1];
#pragma unroll
    for (int m = 0; m < MM; m++) {
        hp[m] = __ldg(hpg + P * 3 + m);
        hn[m] = __ldg(hng + P * 3 + m);
    }
    float* zs = sm + Z_OFF;
#pragma unroll
    for (int s = 0; s < (64 * TILE_M) / NTHREADS; s++) {
        const int it = tid + s * NTHREADS;
        const int k = it & 63;
        const int r = it >> 6;
        const float* xb = gx + (size_t)r * 1024 + k * W21 + LI;
        float* zcol = zs + (k * NZ) * Z_STRIDE + r;
        zcol[0] = h0 * __ldg(xb);
#pragma unroll
        for (int m = 1; m <= MM; m++) {
            const float xp = __ldg(xb + m);
            const float xn = __ldg(xb - m);
            zcol[(2 * m - 1) * Z_STRIDE] = hp[m - 1] * xp + hn[m - 1] * xn;
            zcol[(2 * m) * Z_STRIDE]     = hp[m - 1] * xn - hn[m - 1] * xp;
        }
    }
}

// ---- phase 2: register GEMM. warp rg handles row pairs rg and rg+8;
// lane og handles output channels og*2, og*2+1. f32x2 packs the row pair.
template <int LO, int LI>
__device__ __forceinline__ void gemm(
    const float* __restrict__ sm,
    unsigned long long (&acc)[2][2][2 * LO + 1], int rg, int og)
{
    constexpr int MM = LO < LI ? LO : LI;
    constexpr int NZ = 2 * MM + 1;
    const unsigned long long* zb =
        reinterpret_cast<const unsigned long long*>(sm + Z_OFF);
    const float* wsl = sm + W_OFF + og * 2;
#pragma unroll 4
    for (int k = 0; k < 64; k++) {
        const float2 wv = *reinterpret_cast<const float2*>(wsl + k * W_STRIDE);
        const unsigned long long w0 = dup2(wv.x);
        const unsigned long long w1 = dup2(wv.y);
#pragma unroll
        for (int zc = 0; zc < NZ; zc++) {
            const int c = (zc == 0) ? LO
                         : ((zc & 1) ? LO + (zc + 1) / 2 : LO - zc / 2);
            const int col = k * NZ + zc;
            const unsigned long long zA = zb[col * (Z_STRIDE / 2) + rg];
            const unsigned long long zB = zb[col * (Z_STRIDE / 2) + rg + 8];
            fma2(acc[0][0][c], zA, w0);
            fma2(acc[0][1][c], zA, w1);
            fma2(acc[1][0][c], zB, w0);
            fma2(acc[1][1][c], zB, w1);
        }
    }
}

template <int LO>
__device__ __forceinline__ void run(
    float* __restrict__ sm, const float* __restrict__ x,
    const float* __restrict__ wts, const float* __restrict__ hz,
    const float* __restrict__ hpg, const float* __restrict__ hng,
    float* __restrict__ out, int tile)
{
    constexpr int NC  = 2 * LO + 1;
    constexpr int SEG = 64 * NC;
    constexpr int NQ  = SEG / 4;
    const int tid = threadIdx.x;
    const int rg  = tid >> 5;
    const int og  = tid & 31;
    const float* gx = x + (size_t)tile * TILE_M * 1024;

    unsigned long long acc[2][2][NC];
#pragma unroll
    for (int a = 0; a < 2; a++)
#pragma unroll
        for (int b = 0; b < 2; b++)
#pragma unroll
            for (int c = 0; c < NC; c++) acc[a][b][c] = 0ull;

    stage_combine<LO, 0>(sm, gx + blk_off(0), wts, hz, hpg, hng);
    __syncthreads();
    gemm<LO, 0>(sm, acc, rg, og);
    __syncthreads();
    stage_combine<LO, 1>(sm, gx + blk_off(1), wts, hz, hpg, hng);
    __syncthreads();
    gemm<LO, 1>(sm, acc, rg, og);
    __syncthreads();
    stage_combine<LO, 2>(sm, gx + blk_off(2), wts, hz, hpg, hng);
    __syncthreads();
    gemm<LO, 2>(sm, acc, rg, og);
    __syncthreads();
    stage_combine<LO, 3>(sm, gx + blk_off(3), wts, hz, hpg, hng);
    __syncthreads();
    gemm<LO, 3>(sm, acc, rg, og);

    // ---- output: stage tile in smem (global layout), coalesced f4 stores ----
    __syncthreads();                      // everyone done reading z
    float* smo = sm + Z_OFF;
#pragma unroll
    for (int pr = 0; pr < 2; pr++) {
        const int rbase = 2 * (rg + pr * 8);
#pragma unroll
        for (int oo = 0; oo < 2; oo++) {
            const int o = og * 2 + oo;
#pragma unroll
            for (int c = 0; c < NC; c++) {
                const unsigned long long v = acc[pr][oo][c];
                smo[rbase * SEG + o * NC + c] =
                    __uint_as_float((unsigned)(v & 0xffffffffu));
                smo[(rbase + 1) * SEG + o * NC + c] =
                    __uint_as_float((unsigned)(v >> 32));
            }
        }
    }
    __syncthreads();
    float* go = out + (size_t)tile * TILE_M * 1024 + blk_off(LO);
#pragma unroll
    for (int rr = 0; rr < TILE_M / 8; rr++) {
        const int r = rg * (TILE_M / 8) + rr;
        for (int j = og; j < NQ; j += 32) {
            *reinterpret_cast<float4*>(go + (size_t)r * 1024 + j * 4) =
                *reinterpret_cast<const float4*>(smo + r * SEG + j * 4);
        }
    }
}

extern "C" __global__ void __launch_bounds__(NTHREADS, 2)
tp_kernel(const float* __restrict__ x, const float* __restrict__ wts,
          const float* __restrict__ hz, const float* __restrict__ hpg,
          const float* __restrict__ hng, float* __restrict__ out)
{
    extern __shared__ float sm[];
    const int tile = blockIdx.y;
    switch (blockIdx.x) {
        case 0: run<0>(sm, x, wts, hz, hpg, hng, out, tile); break;
        case 1: run<1>(sm, x, wts, hz, hpg, hng, out, tile); break;
        case 2: run<2>(sm, x, wts, hz, hpg, hng, out, tile); break;
        default: run<3>(sm, x, wts, hz, hpg, hng, out, tile); break;
    }
}

extern "C" void kernel_launch(void* const* d_in, const int* in_sizes, int n_in,
                              void* d_out, int out_size)
{
    const float* x   = (const float*)d_in[0];
    const float* wts = (const float*)d_in[1];
    const float* hz  = (const float*)d_in[2];
    const float* hpg = (const float*)d_in[3];
    const float* hng = (const float*)d_in[4];
    float* out = (float*)d_out;

    cudaFuncSetAttribute(tp_kernel, cudaFuncAttributeMaxDynamicSharedMemorySize,
                         SMEM_BYTES);
    dim3 grid(4, NROWS / TILE_M);
    tp_kernel<<<grid, NTHREADS, SMEM_BYTES>>>(x, wts, hz, hpg, hng, out);
}

// round 7
// speedup vs baseline: 6.0454x; 1.0018x over previous
// O3onO2 tensor product — fused fp32 kernel, f32x2-packed FMAs, TILE_M=32,
// 2 CTAs/SM (77.8KB smem). Per CTA = one (lo, 32-row tile):
//   per li: [stage W + combine z direct-from-global] -> barrier -> GEMM.
// z layout [col][row] with stride 34 (2-way max write conflicts, 8B-aligned
// row-pair reads). Output staged through smem, float4 stores.
#include <cuda_runtime.h>
#include <cstdint>

#define NROWS    65536
#define TILE_M   32
#define NTHREADS 256
#define W_STRIDE 66
#define Z_STRIDE 34
#define W_OFF    0
#define Z_OFF    4224                       // 64*66 floats for W
#define SMEM_FLOATS (Z_OFF + 64 * 7 * Z_STRIDE)   // 4224 + 15232 = 19456
#define SMEM_BYTES  (SMEM_FLOATS * 4)             // 77824 B -> 2 CTAs/SM

__device__ __forceinline__ constexpr int blk_off(int l) {
    return l == 0 ? 0 : (l == 1 ? 64 : (l == 2 ? 256 : 576));
}

__device__ __forceinline__ unsigned long long dup2(float a) {
    unsigned long long r;
    asm("mov.b64 %0, {%1, %1};" : "=l"(r) : "f"(a));
    return r;
}
__device__ __forceinline__ void fma2(unsigned long long& d,
                                     unsigned long long a,
                                     unsigned long long b) {
    asm("fma.rn.f32x2 %0, %1, %2, %0;" : "+l"(d) : "l"(a), "l"(b));
}

// ---- phase 1 of each li: stage W (transposed, L2-hot) + combine z from global
template <int LO, int LI>
__device__ __forceinline__ void stage_combine(
    float* __restrict__ sm, const float* __restrict__ gx,
    const float* __restrict__ wts, const float* __restrict__ hz,
    const float* __restrict__ hpg, const float* __restrict__ hng)
{
    constexpr int W21 = 2 * LI + 1;
    constexpr int MM  = LO < LI ? LO : LI;
    constexpr int NZ  = 2 * MM + 1;
    constexpr int P   = LO * 4 + LI;
    const int tid = threadIdx.x;

    // stage W transposed: ws[i*66 + o] = W[o][i]   (2-way write conflicts)
    const float* gw = wts + P * 4096;
#pragma unroll
    for (int s = 0; s < 16; s++) {
        const int idx = tid + s * NTHREADS;
        const int o = idx >> 6, i = idx & 63;
        sm[W_OFF + i * W_STRIDE + o] = __ldg(gw + idx);
    }

    // combine: z[k*NZ+zc][r] = h-combo of x[r, k*(2LI+1) + LI +- m]
    const float h0 = __ldg(hz + P);
    float hp[MM ? MM : 1], hn[MM ? MM : 1];
#pragma unroll
    for (int m = 0; m < MM; m++) {
        hp[m] = __ldg(hpg + P * 3 + m);
        hn[m] = __ldg(hng + P * 3 + m);
    }
    float* zs = sm + Z_OFF;
#pragma unroll
    for (int s = 0; s < (64 * TILE_M) / NTHREADS; s++) {
        const int it = tid + s * NTHREADS;
        const int k = it & 63;
        const int r = it >> 6;
        const float* xb = gx + (size_t)r * 1024 + k * W21 + LI;
        float* zcol = zs + (k * NZ) * Z_STRIDE + r;
        zcol[0] = h0 * __ldg(xb);
#pragma unroll
        for (int m = 1; m <= MM; m++) {
            const float xp = __ldg(xb + m);
            const float xn = __ldg(xb - m);
            zcol[(2 * m - 1) * Z_STRIDE] = hp[m - 1] * xp + hn[m - 1] * xn;
            zcol[(2 * m) * Z_STRIDE]     = hp[m - 1] * xn - hn[m - 1] * xp;
        }
    }
}

// ---- phase 2: register GEMM. warp rg handles row pairs rg and rg+8;
// lane og handles output channels og*2, og*2+1. f32x2 packs the row pair.
template <int LO, int LI>
__device__ __forceinline__ void gemm(
    const float* __restrict__ sm,
    unsigned long long (&acc)[2][2][2 * LO + 1], int rg, int og)
{
    constexpr int MM = LO < LI ? LO : LI;
    constexpr int NZ = 2 * MM + 1;
    const unsigned long long* zb =
        reinterpret_cast<const unsigned long long*>(sm + Z_OFF);
    const float* wsl = sm + W_OFF + og * 2;
#pragma unroll 4
    for (int k = 0; k < 64; k++) {
        const float2 wv = *reinterpret_cast<const float2*>(wsl + k * W_STRIDE);
        const unsigned long long w0 = dup2(wv.x);
        const unsigned long long w1 = dup2(wv.y);
#pragma unroll
        for (int zc = 0; zc < NZ; zc++) {
            const int c = (zc == 0) ? LO
                         : ((zc & 1) ? LO + (zc + 1) / 2 : LO - zc / 2);
            const int col = k * NZ + zc;
            const unsigned long long zA = zb[col * (Z_STRIDE / 2) + rg];
            const unsigned long long zB = zb[col * (Z_STRIDE / 2) + rg + 8];
            fma2(acc[0][0][c], zA, w0);
            fma2(acc[0][1][c], zA, w1);
            fma2(acc[1][0][c], zB, w0);
            fma2(acc[1][1][c], zB, w1);
        }
    }
}

template <int LO>
__device__ __forceinline__ void run(
    float* __restrict__ sm, const float* __restrict__ x,
    const float* __restrict__ wts, const float* __restrict__ hz,
    const float* __restrict__ hpg, const float* __restrict__ hng,
    float* __restrict__ out, int tile)
{
    constexpr int NC  = 2 * LO + 1;
    constexpr int SEG = 64 * NC;
    constexpr int NQ  = SEG / 4;
    const int tid = threadIdx.x;
    const int rg  = tid >> 5;
    const int og  = tid & 31;
    const float* gx = x + (size_t)tile * TILE_M * 1024;

    unsigned long long acc[2][2][NC];
#pragma unroll
    for (int a = 0; a < 2; a++)
#pragma unroll
        for (int b = 0; b < 2; b++)
#pragma unroll
            for (int c = 0; c < NC; c++) acc[a][b][c] = 0ull;

    stage_combine<LO, 0>(sm, gx + blk_off(0), wts, hz, hpg, hng);
    __syncthreads();
    gemm<LO, 0>(sm, acc, rg, og);
    __syncthreads();
    stage_combine<LO, 1>(sm, gx + blk_off(1), wts, hz, hpg, hng);
    __syncthreads();
    gemm<LO, 1>(sm, acc, rg, og);
    __syncthreads();
    stage_combine<LO, 2>(sm, gx + blk_off(2), wts, hz, hpg, hng);
    __syncthreads();
    gemm<LO, 2>(sm, acc, rg, og);
    __syncthreads();
    stage_combine<LO, 3>(sm, gx + blk_off(3), wts, hz, hpg, hng);
    __syncthreads();
    gemm<LO, 3>(sm, acc, rg, og);

    // ---- output: stage tile in smem (global layout), coalesced f4 stores ----
    __syncthreads();                      // everyone done reading z
    float* smo = sm + Z_OFF;
#pragma unroll
    for (int pr = 0; pr < 2; pr++) {
        const int rbase = 2 * (rg + pr * 8);
#pragma unroll
        for (int oo = 0; oo < 2; oo++) {
            const int o = og * 2 + oo;
#pragma unroll
            for (int c = 0; c < NC; c++) {
                const unsigned long long v = acc[pr][oo][c];
                smo[rbase * SEG + o * NC + c] =
                    __uint_as_float((unsigned)(v & 0xffffffffu));
                smo[(rbase + 1) * SEG + o * NC + c] =
                    __uint_as_float((unsigned)(v >> 32));
            }
        }
    }
    __syncthreads();
    float* go = out + (size_t)tile * TILE_M * 1024 + blk_off(LO);
#pragma unroll
    for (int rr = 0; rr < TILE_M / 8; rr++) {
        const int r = rg * (TILE_M / 8) + rr;
        for (int j = og; j < NQ; j += 32) {
            *reinterpret_cast<float4*>(go + (size_t)r * 1024 + j * 4) =
                *reinterpret_cast<const float4*>(smo + r * SEG + j * 4);
        }
    }
}

extern "C" __global__ void __launch_bounds__(NTHREADS, 2)
tp_kernel(const float* __restrict__ x, const float* __restrict__ wts,
          const float* __restrict__ hz, const float* __restrict__ hpg,
          const float* __restrict__ hng, float* __restrict__ out)
{
    extern __shared__ float sm[];
    const int tile = blockIdx.y;
    switch (blockIdx.x) {
        case 0: run<0>(sm, x, wts, hz, hpg, hng, out, tile); break;
        case 1: run<1>(sm, x, wts, hz, hpg, hng, out, tile); break;
        case 2: run<2>(sm, x, wts, hz, hpg, hng, out, tile); break;
        default: run<3>(sm, x, wts, hz, hpg, hng, out, tile); break;
    }
}

extern "C" void kernel_launch(void* const* d_in, const int* in_sizes, int n_in,
                              void* d_out, int out_size)
{
    const float* x   = (const float*)d_in[0];
    const float* wts = (const float*)d_in[1];
    const float* hz  = (const float*)d_in[2];
    const float* hpg = (const float*)d_in[3];
    const float* hng = (const float*)d_in[4];
    float* out = (float*)d_out;

    cudaFuncSetAttribute(tp_kernel, cudaFuncAttributeMaxDynamicSharedMemorySize,
                         SMEM_BYTES);
    dim3 grid(4, NROWS / TILE_M);
    tp_kernel<<<grid, NTHREADS, SMEM_BYTES>>>(x, wts, hz, hpg, hng, out);
}